// round 2
// baseline (speedup 1.0000x reference)
#include <cuda_runtime.h>
#include <cstdint>

#define NPIX (512*512)   // 262144 pixels
#define CZ 128
#define CT 64
#define NTPL 4           // Nt templates
#define NH 4             // heads
#define DH 32            // per-head dim

// ---------------- device scratch (statics; no runtime allocation) ----------------
__device__ __align__(256) float g_Ac[128 * 256];          // [kz=128][h*64+c=256]
__device__ __align__(256) float g_Bc[256 * 128];          // [h*64+c=256][n=128]
__device__ __align__(256) float g_U[(size_t)NPIX * 256];  // 256 MB
__device__ __align__(256) float g_M[(size_t)NPIX * 256];  // 256 MB

// ---------------- packed f32x2 helpers ----------------
__device__ __forceinline__ unsigned long long fma2(unsigned long long a,
                                                   unsigned long long b,
                                                   unsigned long long c) {
    unsigned long long d;
    asm("fma.rn.f32x2 %0, %1, %2, %3;" : "=l"(d) : "l"(a), "l"(b), "l"(c));
    return d;
}
__device__ __forceinline__ unsigned long long add2(unsigned long long a,
                                                   unsigned long long b) {
    unsigned long long d;
    asm("add.rn.f32x2 %0, %1, %2;" : "=l"(d) : "l"(a), "l"(b));
    return d;
}
__device__ __forceinline__ unsigned long long dup2(float x) {
    unsigned long long d;
    asm("mov.b64 %0, {%1, %1};" : "=l"(d) : "f"(x));
    return d;
}

// ---------------- cp.async helpers ----------------
__device__ __forceinline__ void cp16(uint32_t dst, const float* src) {
    asm volatile("cp.async.cg.shared.global [%0], [%1], 16;" :: "r"(dst), "l"(src));
}
__device__ __forceinline__ void cp_commit() {
    asm volatile("cp.async.commit_group;");
}
template <int N>
__device__ __forceinline__ void cp_wait() {
    asm volatile("cp.async.wait_group %0;" :: "n"(N));
}

// ---------------- weight precombine ----------------
// Ac[kz][h*64+c] = (1/sqrt(32)) * sum_dd wq[kz][h*32+dd] * wk[c][h*32+dd]
// Bc[h*64+c][n]  =               sum_dd wv[c][h*32+dd]  * wo[h*32+dd][n]
__global__ void prep_kernel(const float* __restrict__ wq, const float* __restrict__ wk,
                            const float* __restrict__ wv, const float* __restrict__ wo) {
    int id = blockIdx.x * blockDim.x + threadIdx.x;
    if (id < 128 * 256) {
        int kz = id >> 8;
        int hc = id & 255;
        int h = hc >> 6, c = hc & 63;
        float s = 0.f;
#pragma unroll
        for (int dd = 0; dd < DH; ++dd)
            s += wq[kz * CZ + h * DH + dd] * wk[c * CZ + h * DH + dd];
        g_Ac[id] = s * 0.17677669529663687f;  // 32^-0.5
    } else {
        int e = id - 128 * 256;
        int hc = e >> 7;
        int n = e & 127;
        int h = hc >> 6, c = hc & 63;
        float s = 0.f;
#pragma unroll
        for (int dd = 0; dd < DH; ++dd)
            s += wv[c * CZ + h * DH + dd] * wo[(h * DH + dd) * CZ + n];
        g_Bc[e] = s;
    }
}

// ---------------- weight-stationary fp32 GEMM (f32x2 packed FMA) ----------------
// C[M x N] = A[M x K] @ W[K x N] (+ bias). Tiles: BM=128, BN=128, BK=16.
// MODE 0: A=param(z), W=g_Ac, C=g_U.  MODE 1: A=g_M, W=g_Bc, C=param(out).
template <int K, int N, bool BIAS, int MODE>
__launch_bounds__(256, 2)
__global__ void gemm_kernel(const float* __restrict__ Ain,
                            const float* __restrict__ bias,
                            float* __restrict__ Cout) {
    constexpr int BM = 128, BN = 128, BK = 16;
    constexpr int NTILE = K / BK;

    const float* __restrict__ Ap = (MODE == 0) ? Ain : g_M;
    const float* __restrict__ Wp = (MODE == 0) ? g_Ac : g_Bc;
    float* __restrict__ Cp       = (MODE == 0) ? g_U : Cout;

    __shared__ float As[2][BM][BK];  // [stage][m][k]
    __shared__ float Ws[2][BK][BN];  // [stage][k][n]

    const int mb = blockIdx.x * BM;
    const int nb = blockIdx.y * BN;
    const int tid = threadIdx.x;
    const int tcol = tid & 15;   // 16 cols of threads, 8 outputs each -> BN=128
    const int trow = tid >> 4;   // 16 rows of threads, 8 outputs each -> BM=128

    uint32_t asb = (uint32_t)__cvta_generic_to_shared(&As[0][0][0]);
    uint32_t wsb = (uint32_t)__cvta_generic_to_shared(&Ws[0][0][0]);

    auto load_tile = [&](int kt, int s) {
#pragma unroll
        for (int j = 0; j < 2; ++j) {
            int f = tid + 256 * j;
            int m = f >> 2, q = f & 3;  // A tile: 128 rows x 16 (4x float4/row)
            cp16(asb + (uint32_t)(s * (BM * BK) + m * BK + q * 4) * 4,
                 Ap + (size_t)(mb + m) * K + kt * BK + q * 4);
        }
#pragma unroll
        for (int j = 0; j < 2; ++j) {
            int f = tid + 256 * j;
            int kr = f >> 5, nq = f & 31;  // W tile: 16 rows x 128 (32x float4/row)
            cp16(wsb + (uint32_t)(s * (BK * BN) + kr * BN + nq * 4) * 4,
                 Wp + (size_t)(kt * BK + kr) * N + nb + nq * 4);
        }
        cp_commit();
    };

    unsigned long long acc[8][4];
#pragma unroll
    for (int i = 0; i < 8; ++i)
#pragma unroll
        for (int j = 0; j < 4; ++j) acc[i][j] = 0ull;

    load_tile(0, 0);

    for (int it = 0; it < NTILE; ++it) {
        int s = it & 1;
        if (it + 1 < NTILE) {
            load_tile(it + 1, s ^ 1);
            cp_wait<1>();
        } else {
            cp_wait<0>();
        }
        __syncthreads();

#pragma unroll
        for (int k = 0; k < BK; ++k) {
            unsigned long long a2[8];
#pragma unroll
            for (int i = 0; i < 8; ++i) a2[i] = dup2(As[s][trow * 8 + i][k]);
            ulonglong2 w01 = *reinterpret_cast<const ulonglong2*>(&Ws[s][k][tcol * 8]);
            ulonglong2 w23 = *reinterpret_cast<const ulonglong2*>(&Ws[s][k][tcol * 8 + 4]);
            unsigned long long w2[4] = {w01.x, w01.y, w23.x, w23.y};
#pragma unroll
            for (int i = 0; i < 8; ++i)
#pragma unroll
                for (int j = 0; j < 4; ++j) acc[i][j] = fma2(a2[i], w2[j], acc[i][j]);
        }
        __syncthreads();
    }

    // epilogue
    unsigned long long b2[4];
    if (BIAS) {
        const ulonglong2* bp = reinterpret_cast<const ulonglong2*>(bias + nb + tcol * 8);
        ulonglong2 bb0 = bp[0], bb1 = bp[1];
        b2[0] = bb0.x; b2[1] = bb0.y; b2[2] = bb1.x; b2[3] = bb1.y;
    }
#pragma unroll
    for (int i = 0; i < 8; ++i) {
        size_t off = (size_t)(mb + trow * 8 + i) * N + nb + tcol * 8;
        unsigned long long v0 = acc[i][0], v1 = acc[i][1], v2 = acc[i][2], v3 = acc[i][3];
        if (BIAS) {
            v0 = add2(v0, b2[0]); v1 = add2(v1, b2[1]);
            v2 = add2(v2, b2[2]); v3 = add2(v3, b2[3]);
        }
        ulonglong2 o0; o0.x = v0; o0.y = v1;
        ulonglong2 o1; o1.x = v2; o1.y = v3;
        *reinterpret_cast<ulonglong2*>(&Cp[off]) = o0;
        *reinterpret_cast<ulonglong2*>(&Cp[off + 4]) = o1;
    }
}

// ---------------- per-pixel attention (warp per pixel) ----------------
// Reads g_U[p][256], t[nt][p][64], mask[4]; writes g_M[p][256].
__global__ void attn_kernel(const float* __restrict__ t, const float* __restrict__ mask) {
    int warp = blockIdx.x * 8 + (threadIdx.x >> 5);
    int l = threadIdx.x & 31;
    int p = warp;  // grid sized exactly: 32768 blocks * 8 warps = 262144

    // per-lane slices: lane owns c = j*32 + l (j = 0,1) within each 64-wide chunk
    float uh[NH][2];
#pragma unroll
    for (int h = 0; h < NH; ++h)
#pragma unroll
        for (int j = 0; j < 2; ++j)
            uh[h][j] = g_U[(size_t)p * 256 + h * 64 + j * 32 + l];

    float tt[NTPL][2];
#pragma unroll
    for (int nt = 0; nt < NTPL; ++nt)
#pragma unroll
        for (int j = 0; j < 2; ++j)
            tt[nt][j] = t[((size_t)nt * NPIX + p) * CT + j * 32 + l];

    // partial logits then warp butterfly reduce
    float lg[NH][NTPL];
#pragma unroll
    for (int h = 0; h < NH; ++h)
#pragma unroll
        for (int nt = 0; nt < NTPL; ++nt)
            lg[h][nt] = uh[h][0] * tt[nt][0] + uh[h][1] * tt[nt][1];

#pragma unroll
    for (int off = 16; off > 0; off >>= 1)
#pragma unroll
        for (int h = 0; h < NH; ++h)
#pragma unroll
            for (int nt = 0; nt < NTPL; ++nt)
                lg[h][nt] += __shfl_xor_sync(0xFFFFFFFFu, lg[h][nt], off);

    // additive mask bias
    float bias[NTPL];
#pragma unroll
    for (int nt = 0; nt < NTPL; ++nt) bias[nt] = 100000.0f * (mask[nt] - 1.0f);
#pragma unroll
    for (int h = 0; h < NH; ++h)
#pragma unroll
        for (int nt = 0; nt < NTPL; ++nt) lg[h][nt] += bias[nt];

    // softmax over templates + weighted combine
    float at[NH][NTPL];
#pragma unroll
    for (int h = 0; h < NH; ++h) {
        float mx = fmaxf(fmaxf(lg[h][0], lg[h][1]), fmaxf(lg[h][2], lg[h][3]));
        float e0 = __expf(lg[h][0] - mx);
        float e1 = __expf(lg[h][1] - mx);
        float e2 = __expf(lg[h][2] - mx);
        float e3 = __expf(lg[h][3] - mx);
        float inv = __fdividef(1.0f, e0 + e1 + e2 + e3);
        at[h][0] = e0 * inv; at[h][1] = e1 * inv;
        at[h][2] = e2 * inv; at[h][3] = e3 * inv;
    }

#pragma unroll
    for (int h = 0; h < NH; ++h)
#pragma unroll
        for (int j = 0; j < 2; ++j) {
            float m = at[h][0] * tt[0][j] + at[h][1] * tt[1][j] +
                      at[h][2] * tt[2][j] + at[h][3] * tt[3][j];
            g_M[(size_t)p * 256 + h * 64 + j * 32 + l] = m;
        }
}

// ---------------- launch ----------------
extern "C" void kernel_launch(void* const* d_in, const int* in_sizes, int n_in,
                              void* d_out, int out_size) {
    const float* t    = (const float*)d_in[0];
    const float* z    = (const float*)d_in[1];
    const float* mask = (const float*)d_in[2];
    const float* wq   = (const float*)d_in[3];
    const float* wk   = (const float*)d_in[4];
    const float* wv   = (const float*)d_in[5];
    const float* wo   = (const float*)d_in[6];
    const float* bo   = (const float*)d_in[7];
    float* out = (float*)d_out;

    // 1. precombine weights: Ac = wq_h wk_h^T / sqrt(d), Bc = wv_h wo_h
    prep_kernel<<<256, 256>>>(wq, wk, wv, wo);

    // 2. U = Z @ Ac   (262144 x 256, K=128)
    gemm_kernel<128, 256, false, 0><<<dim3(NPIX / 128, 2), 256>>>(z, nullptr, nullptr);

    // 3. per-pixel attention: U, t, mask -> M
    attn_kernel<<<NPIX / 8, 256>>>(t, mask);

    // 4. out = M @ Bc + bo   (262144 x 128, K=256)
    gemm_kernel<256, 128, true, 1><<<dim3(NPIX / 128, 1), 256>>>(nullptr, bo, out);
}

// round 4
// speedup vs baseline: 1.0231x; 1.0231x over previous
#include <cuda_runtime.h>
#include <cuda_bf16.h>
#include <cstdint>

#define NPIX (512*512)
#define CZ 128
#define CT 64
#define NTPL 4
#define NH 4
#define DH 32

// ---------------- device scratch ----------------
__device__ __align__(256) float g_U[(size_t)NPIX * 256];  // 256 MB
__device__ __align__(256) float g_M[(size_t)NPIX * 256];  // 256 MB
// combined weights, bf16 hi/lo, [n][k] row-major
__device__ __align__(256) __nv_bfloat16 g_W1h[2 * 128 * 128];  // [nh][n][kz]
__device__ __align__(256) __nv_bfloat16 g_W1l[2 * 128 * 128];
__device__ __align__(256) __nv_bfloat16 g_W2h[128 * 256];      // [n][kk]
__device__ __align__(256) __nv_bfloat16 g_W2l[128 * 256];

// ---------------- helpers ----------------
__device__ __forceinline__ uint32_t smem_u32(const void* p) {
    uint32_t a;
    asm("{ .reg .u64 t; cvta.to.shared.u64 t, %1; cvt.u32.u64 %0, t; }" : "=r"(a) : "l"(p));
    return a;
}
__device__ __forceinline__ void ldx4(uint32_t r[4], uint32_t addr) {
    asm volatile("ldmatrix.sync.aligned.m8n8.x4.shared.b16 {%0,%1,%2,%3}, [%4];"
                 : "=r"(r[0]), "=r"(r[1]), "=r"(r[2]), "=r"(r[3]) : "r"(addr));
}
__device__ __forceinline__ void mma16816(float c[4], const uint32_t a[4],
                                         uint32_t b0, uint32_t b1) {
    asm volatile(
        "mma.sync.aligned.m16n8k16.row.col.f32.bf16.bf16.f32 "
        "{%0,%1,%2,%3}, {%4,%5,%6,%7}, {%8,%9}, {%0,%1,%2,%3};"
        : "+f"(c[0]), "+f"(c[1]), "+f"(c[2]), "+f"(c[3])
        : "r"(a[0]), "r"(a[1]), "r"(a[2]), "r"(a[3]), "r"(b0), "r"(b1));
}
__device__ __forceinline__ uint32_t pack_bf2(float x, float y) {
    __nv_bfloat162 p = __halves2bfloat162(__float2bfloat16(x), __float2bfloat16(y));
    return *(uint32_t*)&p;
}

// ---------------- prep: combined weights, bf16 hi/lo split ----------------
// W1[nh][n][kz] = Ac[kz][nh*128+n],  Ac[kz][h*64+c] = sum_dd wq[kz][h*32+dd] wk[c][h*32+dd] / sqrt(32)
// W2[n][kk]     = Bc[kk][n],         Bc[h*64+c][n]  = sum_dd wv[c][h*32+dd] wo[(h*32+dd)][n]
__global__ void prep_kernel(const float* __restrict__ wq, const float* __restrict__ wk,
                            const float* __restrict__ wv, const float* __restrict__ wo) {
    int id = blockIdx.x * blockDim.x + threadIdx.x;
    float val;
    __nv_bfloat16 *dh, *dl;
    int idx;
    if (id < 32768) {
        int kz = id & 127, n = (id >> 7) & 127, nh = id >> 14;
        int hc = nh * 128 + n;
        int h = hc >> 6, c = hc & 63;
        float s = 0.f;
#pragma unroll
        for (int dd = 0; dd < DH; ++dd)
            s += wq[kz * CZ + h * DH + dd] * wk[c * CZ + h * DH + dd];
        val = s * 0.17677669529663687f;
        dh = g_W1h; dl = g_W1l; idx = id;
    } else {
        int e = id - 32768;
        int kk = e & 255, n = e >> 8;
        int h = kk >> 6, c = kk & 63;
        float s = 0.f;
#pragma unroll
        for (int dd = 0; dd < DH; ++dd)
            s += wv[c * CZ + h * DH + dd] * wo[(h * DH + dd) * CZ + n];
        val = s;
        dh = g_W2h; dl = g_W2l; idx = e;
    }
    __nv_bfloat16 hi = __float2bfloat16(val);
    __nv_bfloat16 lo = __float2bfloat16(val - __bfloat162float(hi));
    dh[idx] = hi;
    dl[idx] = lo;
}

// ---------------- mma.sync bf16-split GEMM ----------------
// CTA tile 128x128, 512 threads (4x4 warps, warp tile 32x32), BK=32, double-buffered.
// smem (halves): A[ver][stg] at ((ver*2+stg)*5120), W at 20480 + ((ver*2+stg)*5120)
// row pitch 40 halves (80B) -> conflict-free ldmatrix.
static constexpr int SMEM_BYTES = 81920;

template <int NCHUNK, int ASTRIDE, int KW, int CSTRIDE, bool BIAS, int MODE>
__global__ __launch_bounds__(512, 1) void tgemm(const float* __restrict__ Ain,
                                                const float* __restrict__ bias,
                                                float* __restrict__ Cout) {
    extern __shared__ __nv_bfloat16 sm[];
    const int tid = threadIdx.x;
    const int lane = tid & 31;
    const int wid = tid >> 5;
    const int mw = wid & 3, nw = wid >> 2;
    const int pb = blockIdx.x * 128;
    const int nh = (MODE == 0) ? blockIdx.y : 0;
    const int colbase = (MODE == 0) ? nh * 128 : 0;

    const float* __restrict__ Ap = (MODE == 0) ? Ain : g_M;
    const __nv_bfloat16* __restrict__ Wh = (MODE == 0) ? g_W1h + nh * 16384 : g_W2h;
    const __nv_bfloat16* __restrict__ Wl = (MODE == 0) ? g_W1l + nh * 16384 : g_W2l;
    float* __restrict__ Cp = (MODE == 0) ? g_U : Cout;

    const uint32_t sbase = smem_u32(sm);

    // load indices
    const int ap = tid >> 3, aq = tid & 7;          // A: row ap (and ap+64), float4 col aq
    const int wn = tid >> 2, wc = tid & 3;          // W: row wn, 16B chunk wc

    float4 pa0, pa1;
    uint4 pwh, pwl;
    auto g_load = [&](int kt) {
        pa0 = *(const float4*)(Ap + (size_t)(pb + ap) * ASTRIDE + kt * 32 + aq * 4);
        pa1 = *(const float4*)(Ap + (size_t)(pb + ap + 64) * ASTRIDE + kt * 32 + aq * 4);
        pwh = *(const uint4*)(Wh + (size_t)wn * KW + kt * 32 + wc * 8);
        pwl = *(const uint4*)(Wl + (size_t)wn * KW + kt * 32 + wc * 8);
    };
    auto s_store = [&](int stg) {
        // A hi / lo
        uint32_t off0 = ap * 40 + aq * 4;
        uint32_t off1 = (ap + 64) * 40 + aq * 4;
        uint2 h0, l0, h1, l1;
        h0.x = pack_bf2(pa0.x, pa0.y); h0.y = pack_bf2(pa0.z, pa0.w);
        {
            float rx = pa0.x - __bfloat162float(__float2bfloat16(pa0.x));
            float ry = pa0.y - __bfloat162float(__float2bfloat16(pa0.y));
            float rz = pa0.z - __bfloat162float(__float2bfloat16(pa0.z));
            float rw = pa0.w - __bfloat162float(__float2bfloat16(pa0.w));
            l0.x = pack_bf2(rx, ry); l0.y = pack_bf2(rz, rw);
        }
        h1.x = pack_bf2(pa1.x, pa1.y); h1.y = pack_bf2(pa1.z, pa1.w);
        {
            float rx = pa1.x - __bfloat162float(__float2bfloat16(pa1.x));
            float ry = pa1.y - __bfloat162float(__float2bfloat16(pa1.y));
            float rz = pa1.z - __bfloat162float(__float2bfloat16(pa1.z));
            float rw = pa1.w - __bfloat162float(__float2bfloat16(pa1.w));
            l1.x = pack_bf2(rx, ry); l1.y = pack_bf2(rz, rw);
        }
        *(uint2*)(sm + stg * 5120 + off0) = h0;
        *(uint2*)(sm + (2 + stg) * 5120 + off0) = l0;
        *(uint2*)(sm + stg * 5120 + off1) = h1;
        *(uint2*)(sm + (2 + stg) * 5120 + off1) = l1;
        // W hi / lo
        uint32_t woff = wn * 40 + wc * 8;
        *(uint4*)(sm + 20480 + stg * 5120 + woff) = pwh;
        *(uint4*)(sm + 20480 + (2 + stg) * 5120 + woff) = pwl;
    };

    float acc[2][4][4];
#pragma unroll
    for (int i = 0; i < 2; ++i)
#pragma unroll
        for (int j = 0; j < 4; ++j)
#pragma unroll
            for (int q = 0; q < 4; ++q) acc[i][j][q] = 0.f;

    const int lrow = lane & 15;
    const int lkb = (lane >> 4) * 16;  // byte offset 0 or 16

    g_load(0);
    s_store(0);
    __syncthreads();

    for (int kt = 0; kt < NCHUNK; ++kt) {
        const int stg = kt & 1;
        if (kt + 1 < NCHUNK) g_load(kt + 1);

        const uint32_t aH = sbase + (stg * 5120) * 2;
        const uint32_t aL = sbase + ((2 + stg) * 5120) * 2;
        const uint32_t wH = sbase + ((20480 + stg * 5120)) * 2;
        const uint32_t wL = sbase + ((20480 + (2 + stg) * 5120)) * 2;

#pragma unroll
        for (int k16 = 0; k16 < 2; ++k16) {
            const uint32_t kbyte = k16 * 32 + lkb;
            uint32_t ah[2][4], al[2][4], bh[2][4], bl[2][4];
#pragma unroll
            for (int mb = 0; mb < 2; ++mb) {
                uint32_t off = (uint32_t)(mw * 32 + mb * 16 + lrow) * 80 + kbyte;
                ldx4(ah[mb], aH + off);
                ldx4(al[mb], aL + off);
            }
#pragma unroll
            for (int ng = 0; ng < 2; ++ng) {
                uint32_t off = (uint32_t)(nw * 32 + ng * 16 + lrow) * 80 + kbyte;
                ldx4(bh[ng], wH + off);
                ldx4(bl[ng], wL + off);
            }
#pragma unroll
            for (int mb = 0; mb < 2; ++mb)
#pragma unroll
                for (int nb = 0; nb < 4; ++nb) {
                    const int ng = nb >> 1, hf = nb & 1;
                    mma16816(acc[mb][nb], ah[mb], bh[ng][hf], bh[ng][2 + hf]);
                    mma16816(acc[mb][nb], ah[mb], bl[ng][hf], bl[ng][2 + hf]);
                    mma16816(acc[mb][nb], al[mb], bh[ng][hf], bh[ng][2 + hf]);
                }
        }

        if (kt + 1 < NCHUNK) {
            __syncthreads();
            s_store((kt + 1) & 1);
            __syncthreads();
        }
    }

    // epilogue: direct float2 stores
    const int r4 = lane >> 2, c2 = (lane & 3) * 2;
#pragma unroll
    for (int mb = 0; mb < 2; ++mb)
#pragma unroll
        for (int nb = 0; nb < 4; ++nb) {
            int row = pb + mw * 32 + mb * 16 + r4;
            int col = colbase + nw * 32 + nb * 8 + c2;
            float2 v0 = make_float2(acc[mb][nb][0], acc[mb][nb][1]);
            float2 v1 = make_float2(acc[mb][nb][2], acc[mb][nb][3]);
            if (BIAS) {
                float2 b = *(const float2*)(bias + col);
                v0.x += b.x; v0.y += b.y; v1.x += b.x; v1.y += b.y;
            }
            *(float2*)(&Cp[(size_t)row * CSTRIDE + col]) = v0;
            *(float2*)(&Cp[(size_t)(row + 8) * CSTRIDE + col]) = v1;
        }
}

// ---------------- per-pixel attention (warp per pixel) ----------------
__global__ void attn_kernel(const float* __restrict__ t, const float* __restrict__ mask) {
    int warp = blockIdx.x * 8 + (threadIdx.x >> 5);
    int l = threadIdx.x & 31;
    int p = warp;

    float uh[NH][2];
#pragma unroll
    for (int h = 0; h < NH; ++h)
#pragma unroll
        for (int j = 0; j < 2; ++j)
            uh[h][j] = g_U[(size_t)p * 256 + h * 64 + j * 32 + l];

    float tt[NTPL][2];
#pragma unroll
    for (int nt = 0; nt < NTPL; ++nt)
#pragma unroll
        for (int j = 0; j < 2; ++j)
            tt[nt][j] = t[((size_t)nt * NPIX + p) * CT + j * 32 + l];

    float lg[NH][NTPL];
#pragma unroll
    for (int h = 0; h < NH; ++h)
#pragma unroll
        for (int nt = 0; nt < NTPL; ++nt)
            lg[h][nt] = uh[h][0] * tt[nt][0] + uh[h][1] * tt[nt][1];

#pragma unroll
    for (int off = 16; off > 0; off >>= 1)
#pragma unroll
        for (int h = 0; h < NH; ++h)
#pragma unroll
            for (int nt = 0; nt < NTPL; ++nt)
                lg[h][nt] += __shfl_xor_sync(0xFFFFFFFFu, lg[h][nt], off);

    float bias[NTPL];
#pragma unroll
    for (int nt = 0; nt < NTPL; ++nt) bias[nt] = 100000.0f * (mask[nt] - 1.0f);
#pragma unroll
    for (int h = 0; h < NH; ++h)
#pragma unroll
        for (int nt = 0; nt < NTPL; ++nt) lg[h][nt] += bias[nt];

    float at[NH][NTPL];
#pragma unroll
    for (int h = 0; h < NH; ++h) {
        float mx = fmaxf(fmaxf(lg[h][0], lg[h][1]), fmaxf(lg[h][2], lg[h][3]));
        float e0 = __expf(lg[h][0] - mx);
        float e1 = __expf(lg[h][1] - mx);
        float e2 = __expf(lg[h][2] - mx);
        float e3 = __expf(lg[h][3] - mx);
        float inv = __fdividef(1.0f, e0 + e1 + e2 + e3);
        at[h][0] = e0 * inv; at[h][1] = e1 * inv;
        at[h][2] = e2 * inv; at[h][3] = e3 * inv;
    }

#pragma unroll
    for (int h = 0; h < NH; ++h)
#pragma unroll
        for (int j = 0; j < 2; ++j) {
            float m = at[h][0] * tt[0][j] + at[h][1] * tt[1][j] +
                      at[h][2] * tt[2][j] + at[h][3] * tt[3][j];
            g_M[(size_t)p * 256 + h * 64 + j * 32 + l] = m;
        }
}

// ---------------- launch ----------------
extern "C" void kernel_launch(void* const* d_in, const int* in_sizes, int n_in,
                              void* d_out, int out_size) {
    const float* t    = (const float*)d_in[0];
    const float* z    = (const float*)d_in[1];
    const float* mask = (const float*)d_in[2];
    const float* wq   = (const float*)d_in[3];
    const float* wk   = (const float*)d_in[4];
    const float* wv   = (const float*)d_in[5];
    const float* wo   = (const float*)d_in[6];
    const float* bo   = (const float*)d_in[7];
    float* out = (float*)d_out;

    cudaFuncSetAttribute(tgemm<4, 128, 128, 256, false, 0>,
                         cudaFuncAttributeMaxDynamicSharedMemorySize, SMEM_BYTES);
    cudaFuncSetAttribute(tgemm<8, 256, 256, 128, true, 1>,
                         cudaFuncAttributeMaxDynamicSharedMemorySize, SMEM_BYTES);

    // 1. precombine + bf16-split weights
    prep_kernel<<<256, 256>>>(wq, wk, wv, wo);

    // 2. U = Z @ Ac  (mma.sync bf16-split), 2048 pixel tiles x 2 N-halves
    tgemm<4, 128, 128, 256, false, 0>
        <<<dim3(NPIX / 128, 2), 512, SMEM_BYTES>>>(z, nullptr, nullptr);

    // 3. per-pixel attention: U, t, mask -> M
    attn_kernel<<<NPIX / 8, 256>>>(t, mask);

    // 4. out = M @ Bc + bo
    tgemm<8, 256, 256, 128, true, 1>
        <<<dim3(NPIX / 128, 1), 512, SMEM_BYTES>>>(nullptr, bo, out);
}

// round 6
// speedup vs baseline: 1.5200x; 1.4857x over previous
#include <cuda_runtime.h>
#include <cuda_bf16.h>
#include <cstdint>

#define NPIX (512*512)
#define CZ 128
#define CT 64
#define NTPL 4
#define NH 4
#define DH 32

// ---------------- device scratch ----------------
__device__ __align__(256) float g_U[(size_t)NPIX * 256];               // 256 MB fp32
__device__ __align__(256) __nv_bfloat16 g_zh[(size_t)NPIX * 128];      // z hi
__device__ __align__(256) __nv_bfloat16 g_zl[(size_t)NPIX * 128];      // z lo
__device__ __align__(256) __nv_bfloat16 g_Mh[(size_t)NPIX * 256];      // M hi
__device__ __align__(256) __nv_bfloat16 g_Ml[(size_t)NPIX * 256];      // M lo
// combined weights, bf16 hi/lo, [n][k] row-major
__device__ __align__(256) __nv_bfloat16 g_W1h[2 * 128 * 128];          // [nh][n][kz]
__device__ __align__(256) __nv_bfloat16 g_W1l[2 * 128 * 128];
__device__ __align__(256) __nv_bfloat16 g_W2h[128 * 256];              // [n][kk]
__device__ __align__(256) __nv_bfloat16 g_W2l[128 * 256];

// ---------------- helpers ----------------
__device__ __forceinline__ uint32_t smem_u32(const void* p) {
    uint32_t a;
    asm("{ .reg .u64 t; cvta.to.shared.u64 t, %1; cvt.u32.u64 %0, t; }" : "=r"(a) : "l"(p));
    return a;
}
__device__ __forceinline__ void ldx4(uint32_t r[4], uint32_t addr) {
    asm volatile("ldmatrix.sync.aligned.m8n8.x4.shared.b16 {%0,%1,%2,%3}, [%4];"
                 : "=r"(r[0]), "=r"(r[1]), "=r"(r[2]), "=r"(r[3]) : "r"(addr));
}
__device__ __forceinline__ void mma16816(float c[4], const uint32_t a[4],
                                         uint32_t b0, uint32_t b1) {
    asm volatile(
        "mma.sync.aligned.m16n8k16.row.col.f32.bf16.bf16.f32 "
        "{%0,%1,%2,%3}, {%4,%5,%6,%7}, {%8,%9}, {%0,%1,%2,%3};"
        : "+f"(c[0]), "+f"(c[1]), "+f"(c[2]), "+f"(c[3])
        : "r"(a[0]), "r"(a[1]), "r"(a[2]), "r"(a[3]), "r"(b0), "r"(b1));
}
__device__ __forceinline__ uint32_t pack_bf2(float x, float y) {
    __nv_bfloat162 p = __halves2bfloat162(__float2bfloat16(x), __float2bfloat16(y));
    return *(uint32_t*)&p;
}
__device__ __forceinline__ void cp16(uint32_t dst, const void* src) {
    asm volatile("cp.async.cg.shared.global [%0], [%1], 16;" :: "r"(dst), "l"(src));
}
__device__ __forceinline__ void cp_commit() { asm volatile("cp.async.commit_group;"); }
__device__ __forceinline__ void cp_wait0() {
    asm volatile("cp.async.wait_group 0;" ::: "memory");
}

// ---------------- prep: combined weights, bf16 hi/lo split ----------------
__global__ void prep_kernel(const float* __restrict__ wq, const float* __restrict__ wk,
                            const float* __restrict__ wv, const float* __restrict__ wo) {
    int id = blockIdx.x * blockDim.x + threadIdx.x;
    float val;
    __nv_bfloat16 *dh, *dl;
    int idx;
    if (id < 32768) {
        int kz = id & 127, n = (id >> 7) & 127, nh = id >> 14;
        int hc = nh * 128 + n;
        int h = hc >> 6, c = hc & 63;
        float s = 0.f;
#pragma unroll
        for (int dd = 0; dd < DH; ++dd)
            s += wq[kz * CZ + h * DH + dd] * wk[c * CZ + h * DH + dd];
        val = s * 0.17677669529663687f;
        dh = g_W1h; dl = g_W1l; idx = id;
    } else {
        int e = id - 32768;
        int kk = e & 255, n = e >> 8;
        int h = kk >> 6, c = kk & 63;
        float s = 0.f;
#pragma unroll
        for (int dd = 0; dd < DH; ++dd)
            s += wv[c * CZ + h * DH + dd] * wo[(h * DH + dd) * CZ + n];
        val = s;
        dh = g_W2h; dl = g_W2l; idx = e;
    }
    __nv_bfloat16 hi = __float2bfloat16(val);
    __nv_bfloat16 lo = __float2bfloat16(val - __bfloat162float(hi));
    dh[idx] = hi;
    dl[idx] = lo;
}

// ---------------- convz: z fp32 -> planar bf16 hi/lo ----------------
__global__ void convz_kernel(const float* __restrict__ z) {
    size_t i = ((size_t)blockIdx.x * 256 + threadIdx.x) * 4;
    float4 v = *(const float4*)(z + i);
    __nv_bfloat16 h0 = __float2bfloat16(v.x), h1 = __float2bfloat16(v.y);
    __nv_bfloat16 h2 = __float2bfloat16(v.z), h3 = __float2bfloat16(v.w);
    uint2 ph, pl;
    ph.x = pack_bf2(v.x, v.y); ph.y = pack_bf2(v.z, v.w);
    pl.x = pack_bf2(v.x - __bfloat162float(h0), v.y - __bfloat162float(h1));
    pl.y = pack_bf2(v.z - __bfloat162float(h2), v.w - __bfloat162float(h3));
    *(uint2*)(g_zh + i) = ph;
    *(uint2*)(g_zl + i) = pl;
}

// ---------------- cp.async double-buffered bf16-split GEMM ----------------
// CTA 128x128, 256 threads, warps 2(M)x4(N), warp tile 64x32, BK=32.
// smem: A planes (hi,lo) x 2 stages @ 10240B each; W same at +40960. 80B row pitch.
static constexpr int GSMEM = 81920;

template <int KTOT, int MODE, bool BIAS>
__global__ __launch_bounds__(256, 2) void tgemm(const float* __restrict__ bias,
                                                float* __restrict__ Cout) {
    extern __shared__ char sm[];
    const uint32_t sbase = smem_u32(sm);
    const int tid = threadIdx.x;
    const int lane = tid & 31;
    const int wid = tid >> 5;
    const int mw = wid & 1, nw = wid >> 1;
    const int pb = blockIdx.x * 128;
    const int nh = (MODE == 0) ? blockIdx.y : 0;
    constexpr int NC = KTOT / 32;

    const __nv_bfloat16* __restrict__ Ah = (MODE == 0) ? g_zh : g_Mh;
    const __nv_bfloat16* __restrict__ Al = (MODE == 0) ? g_zl : g_Ml;
    const __nv_bfloat16* __restrict__ Wh = (MODE == 0) ? g_W1h + nh * 16384 : g_W2h;
    const __nv_bfloat16* __restrict__ Wl = (MODE == 0) ? g_W1l + nh * 16384 : g_W2l;
    float* __restrict__ Cp = (MODE == 0) ? g_U : Cout;
    const int CSTR = (MODE == 0) ? 256 : 128;
    const int colbase = (MODE == 0) ? nh * 128 : 0;

    auto issue = [&](int kt, int s) {
#pragma unroll
        for (int i = 0; i < 4; ++i) {
            int id = tid + 256 * i;                 // 0..1023
            int plane = id >> 9;                    // 0..1
            int r = (id >> 2) & 127;
            int c = id & 3;
            const __nv_bfloat16* asrc = (plane ? Al : Ah)
                + (size_t)(pb + r) * KTOT + kt * 32 + c * 8;
            cp16(sbase + (uint32_t)((s * 2 + plane) * 10240 + r * 80 + c * 16), asrc);
            const __nv_bfloat16* wsrc = (plane ? Wl : Wh)
                + (size_t)r * KTOT + kt * 32 + c * 8;
            cp16(sbase + (uint32_t)(40960 + (s * 2 + plane) * 10240 + r * 80 + c * 16), wsrc);
        }
        cp_commit();
    };

    float acc[4][4][4];
#pragma unroll
    for (int i = 0; i < 4; ++i)
#pragma unroll
        for (int j = 0; j < 4; ++j)
#pragma unroll
            for (int q = 0; q < 4; ++q) acc[i][j][q] = 0.f;

    const int lrow = lane & 15;
    const int lkb = (lane >> 4) * 16;

    issue(0, 0);

    for (int kt = 0; kt < NC; ++kt) {
        const int s = kt & 1;
        cp_wait0();
        __syncthreads();
        if (kt + 1 < NC) issue(kt + 1, s ^ 1);

        const uint32_t aBh = sbase + (uint32_t)(s * 2) * 10240;
        const uint32_t aBl = aBh + 10240;
        const uint32_t wBh = sbase + 40960u + (uint32_t)(s * 2) * 10240;
        const uint32_t wBl = wBh + 10240;

#pragma unroll
        for (int k16 = 0; k16 < 2; ++k16) {
            const uint32_t kbyte = k16 * 32 + lkb;
            uint32_t bh[2][4], bl[2][4];
#pragma unroll
            for (int ng = 0; ng < 2; ++ng) {
                uint32_t off = (uint32_t)(nw * 32 + ng * 16 + lrow) * 80 + kbyte;
                ldx4(bh[ng], wBh + off);
                ldx4(bl[ng], wBl + off);
            }
#pragma unroll
            for (int mb = 0; mb < 4; ++mb) {
                uint32_t off = (uint32_t)(mw * 64 + mb * 16 + lrow) * 80 + kbyte;
                uint32_t ah[4], al[4];
                ldx4(ah, aBh + off);
                ldx4(al, aBl + off);
#pragma unroll
                for (int nb = 0; nb < 4; ++nb) {
                    const int ng = nb >> 1, hf = nb & 1;
                    mma16816(acc[mb][nb], ah, bh[ng][hf], bh[ng][2 + hf]);
                    mma16816(acc[mb][nb], ah, bl[ng][hf], bl[ng][2 + hf]);
                    mma16816(acc[mb][nb], al, bh[ng][hf], bh[ng][2 + hf]);
                }
            }
        }
        __syncthreads();
    }

    // epilogue
    const int r4 = lane >> 2, c2 = (lane & 3) * 2;
#pragma unroll
    for (int mb = 0; mb < 4; ++mb)
#pragma unroll
        for (int nb = 0; nb < 4; ++nb) {
            int row = pb + mw * 64 + mb * 16 + r4;
            int col = colbase + nw * 32 + nb * 8 + c2;
            float2 v0 = make_float2(acc[mb][nb][0], acc[mb][nb][1]);
            float2 v1 = make_float2(acc[mb][nb][2], acc[mb][nb][3]);
            if (BIAS) {
                float2 b = *(const float2*)(bias + col);
                v0.x += b.x; v0.y += b.y; v1.x += b.x; v1.y += b.y;
            }
            *(float2*)(&Cp[(size_t)row * CSTR + col]) = v0;
            *(float2*)(&Cp[(size_t)(row + 8) * CSTR + col]) = v1;
        }
}

// ---------------- per-pixel attention (warp per pixel); emits M as bf16 hi/lo --------
__global__ void attn_kernel(const float* __restrict__ t, const float* __restrict__ mask) {
    int warp = blockIdx.x * 8 + (threadIdx.x >> 5);
    int l = threadIdx.x & 31;
    int p = warp;

    float uh[NH][2];
#pragma unroll
    for (int h = 0; h < NH; ++h)
#pragma unroll
        for (int j = 0; j < 2; ++j)
            uh[h][j] = g_U[(size_t)p * 256 + h * 64 + j * 32 + l];

    float tt[NTPL][2];
#pragma unroll
    for (int nt = 0; nt < NTPL; ++nt)
#pragma unroll
        for (int j = 0; j < 2; ++j)
            tt[nt][j] = t[((size_t)nt * NPIX + p) * CT + j * 32 + l];

    float lg[NH][NTPL];
#pragma unroll
    for (int h = 0; h < NH; ++h)
#pragma unroll
        for (int nt = 0; nt < NTPL; ++nt)
            lg[h][nt] = uh[h][0] * tt[nt][0] + uh[h][1] * tt[nt][1];

#pragma unroll
    for (int off = 16; off > 0; off >>= 1)
#pragma unroll
        for (int h = 0; h < NH; ++h)
#pragma unroll
            for (int nt = 0; nt < NTPL; ++nt)
                lg[h][nt] += __shfl_xor_sync(0xFFFFFFFFu, lg[h][nt], off);

    float bias[NTPL];
#pragma unroll
    for (int nt = 0; nt < NTPL; ++nt) bias[nt] = 100000.0f * (mask[nt] - 1.0f);
#pragma unroll
    for (int h = 0; h < NH; ++h)
#pragma unroll
        for (int nt = 0; nt < NTPL; ++nt) lg[h][nt] += bias[nt];

    float at[NH][NTPL];
#pragma unroll
    for (int h = 0; h < NH; ++h) {
        float mx = fmaxf(fmaxf(lg[h][0], lg[h][1]), fmaxf(lg[h][2], lg[h][3]));
        float e0 = __expf(lg[h][0] - mx);
        float e1 = __expf(lg[h][1] - mx);
        float e2 = __expf(lg[h][2] - mx);
        float e3 = __expf(lg[h][3] - mx);
        float inv = __fdividef(1.0f, e0 + e1 + e2 + e3);
        at[h][0] = e0 * inv; at[h][1] = e1 * inv;
        at[h][2] = e2 * inv; at[h][3] = e3 * inv;
    }

#pragma unroll
    for (int h = 0; h < NH; ++h)
#pragma unroll
        for (int j = 0; j < 2; ++j) {
            float m = at[h][0] * tt[0][j] + at[h][1] * tt[1][j] +
                      at[h][2] * tt[2][j] + at[h][3] * tt[3][j];
            __nv_bfloat16 mh = __float2bfloat16(m);
            __nv_bfloat16 ml = __float2bfloat16(m - __bfloat162float(mh));
            size_t idx = (size_t)p * 256 + h * 64 + j * 32 + l;
            g_Mh[idx] = mh;
            g_Ml[idx] = ml;
        }
}

// ---------------- launch ----------------
extern "C" void kernel_launch(void* const* d_in, const int* in_sizes, int n_in,
                              void* d_out, int out_size) {
    const float* t    = (const float*)d_in[0];
    const float* z    = (const float*)d_in[1];
    const float* mask = (const float*)d_in[2];
    const float* wq   = (const float*)d_in[3];
    const float* wk   = (const float*)d_in[4];
    const float* wv   = (const float*)d_in[5];
    const float* wo   = (const float*)d_in[6];
    const float* bo   = (const float*)d_in[7];
    float* out = (float*)d_out;

    cudaFuncSetAttribute(tgemm<128, 0, false>,
                         cudaFuncAttributeMaxDynamicSharedMemorySize, GSMEM);
    cudaFuncSetAttribute(tgemm<256, 1, true>,
                         cudaFuncAttributeMaxDynamicSharedMemorySize, GSMEM);

    // 1. weights precombine + split; z split
    prep_kernel<<<256, 256>>>(wq, wk, wv, wo);
    convz_kernel<<<NPIX * 128 / 1024, 256>>>(z);

    // 2. U = Z @ Ac
    tgemm<128, 0, false><<<dim3(NPIX / 128, 2), 256, GSMEM>>>(nullptr, nullptr);

    // 3. attention: U, t, mask -> M (bf16 hi/lo)
    attn_kernel<<<NPIX / 8, 256>>>(t, mask);

    // 4. out = M @ Bc + bo
    tgemm<256, 1, true><<<dim3(NPIX / 128, 1), 256, GSMEM>>>(bo, out);
}